// round 15
// baseline (speedup 1.0000x reference)
#include <cuda_runtime.h>
#include <cuda_fp16.h>
#include <math_constants.h>
#include <cstdint>

#define Nn 25000
#define IND 512
#define Hh 8
#define HD 512
#define KEDGE 16   // E/N inbound edges per node (dst = arange(E) % N)
#define LALPHA 0.2f

// ---- GEMM tiling ----
#define MT 128
#define NT 256
#define KC 64
#define NC (IND / KC)    // 8
#define PITCH 144        // 128B data + 16B pad (conflict-free ldmatrix)
#define PLANE_A (128 * PITCH)            // 18432 B
#define PLANE_B (256 * PITCH)            // 36864 B
#define STG (PLANE_A + PLANE_B)          // 55296 B
#define SMEM_SZ (2 * STG)                // 110592 B

// epilogue staging tile: 32 rows x 264 fp16 (528B pitch, conflict-free)
#define TPITCH 264

// Scratch (allocation-free rule: __device__ globals)
__device__ __half g_ft[Nn * HD];       // projected features, fp16
__device__ __half g_Whi[IND * IND];    // fp16(W)
__device__ float  g_a1[Nn * Hh];
__device__ float  g_a2[Nn * Hh];

#define NW4 (IND * IND / 4)

__device__ __forceinline__ uint32_t smem_u32(const void* p) {
    uint32_t a;
    asm("{ .reg .u64 t; cvta.to.shared.u64 t, %1; cvt.u32.u64 %0, t; }" : "=r"(a) : "l"(p));
    return a;
}

#define LDSM4(r, addr) \
    asm volatile("ldmatrix.sync.aligned.m8n8.x4.shared.b16 {%0,%1,%2,%3}, [%4];" \
        : "=r"((r)[0]), "=r"((r)[1]), "=r"((r)[2]), "=r"((r)[3]) : "r"(addr))

#define MMA_F16(c, a, b) \
    asm volatile("mma.sync.aligned.m16n8k16.row.col.f32.f16.f16.f32 " \
        "{%0,%1,%2,%3}, {%4,%5,%6,%7}, {%8,%9}, {%0,%1,%2,%3};" \
        : "+f"((c)[0]), "+f"((c)[1]), "+f"((c)[2]), "+f"((c)[3]) \
        : "r"((a)[0]), "r"((a)[1]), "r"((a)[2]), "r"((a)[3]), "r"((b)[0]), "r"((b)[1]))

#define CP16(dst, src, p) \
    asm volatile("cp.async.cg.shared.global [%0], [%1], 16, %2;" \
        :: "r"(dst), "l"(src), "r"(p) : "memory")
#define CP_COMMIT() asm volatile("cp.async.commit_group;" ::: "memory")
#define CP_WAIT0()  asm volatile("cp.async.wait_group 0;" ::: "memory")

__device__ __forceinline__ uint32_t packf(float a, float b) {
    __half2 h = __floats2half2_rn(a, b);
    return *reinterpret_cast<uint32_t*>(&h);
}

// ---------------------------------------------------------------------------
// Kernel 0: W -> fp16 (tiny: 1.5 MB traffic)
// ---------------------------------------------------------------------------
__global__ __launch_bounds__(256) void gat_splitW(const float* __restrict__ W)
{
    int idx = blockIdx.x * 256 + threadIdx.x;
    if (idx < NW4) {
        float4 v = reinterpret_cast<const float4*>(W)[idx];
        uint2 hp = make_uint2(packf(v.x, v.y), packf(v.z, v.w));
        *reinterpret_cast<uint2*>(&g_Whi[(size_t)idx * 4]) = hp;
    }
}

// ---------------------------------------------------------------------------
// Kernel 1: ft = fp16(A) @ Whi^T, fp16 MMA, fp32 accum. Main loop = R13 exact.
// Epilogue: a1/a2 fused (unchanged) + ft stores staged through smem for
// fully-coalesced STG.128 (replaces strided STG.32).
// grid = (196, 2), 512 threads (16 warps: 2M x 8N).
// ---------------------------------------------------------------------------
__global__ __launch_bounds__(512, 1)
void gat_gemm10(const float* __restrict__ A,
                const float* __restrict__ attn_l,
                const float* __restrict__ attn_r)
{
    extern __shared__ char smem[];
    const uint32_t sb = smem_u32(smem);
    const int tid  = threadIdx.x;
    const int lane = tid & 31;
    const int wid  = tid >> 5;
    const int wm   = wid >> 3;      // 0..1
    const int wn   = wid & 7;       // 0..7
    const int row0 = blockIdx.x * MT;
    const int cblk = blockIdx.y;    // 0..1
    const int col0 = cblk * NT;

    const int r_a = tid >> 2;       // 0..127
    const int qa  = tid & 3;
    const int n_a = row0 + r_a;
    const bool a_ok = (n_a < Nn);
    const float* Abase = &A[(size_t)n_a * IND + qa * 16];

    const int r_ld = tid >> 3;      // 0..63
    const int q_ld = tid & 7;

    float4 ra[4];

    auto ldgA = [&](int c) {
        const int k0 = c * KC;
        if (a_ok) {
            #pragma unroll
            for (int j = 0; j < 4; j++)
                ra[j] = *reinterpret_cast<const float4*>(Abase + k0 + j * 4);
        } else {
            #pragma unroll
            for (int j = 0; j < 4; j++) ra[j] = make_float4(0.f, 0.f, 0.f, 0.f);
        }
    };
    auto stsA = [&](int c) {
        int off = (c & 1) * STG + r_a * PITCH + qa * 32;
        uint4 p0 = make_uint4(packf(ra[0].x, ra[0].y), packf(ra[0].z, ra[0].w),
                              packf(ra[1].x, ra[1].y), packf(ra[1].z, ra[1].w));
        uint4 p1 = make_uint4(packf(ra[2].x, ra[2].y), packf(ra[2].z, ra[2].w),
                              packf(ra[3].x, ra[3].y), packf(ra[3].z, ra[3].w));
        *reinterpret_cast<uint4*>(smem + off)      = p0;
        *reinterpret_cast<uint4*>(smem + off + 16) = p1;
    };
    auto cpB = [&](int c) {
        const int k0 = c * KC;
        const uint32_t base = sb + (uint32_t)((c & 1) * STG) + PLANE_A;
        #pragma unroll
        for (int it = 0; it < 4; it++) {
            int r = r_ld + it * 64;
            uint32_t dst = base + (uint32_t)(r * PITCH + q_ld * 16);
            const __half* sbh = &g_Whi[(size_t)(col0 + r) * IND + k0 + q_ld * 8];
            CP16(dst, sbh, 16);
        }
        CP_COMMIT();
    };

    float acc[4][4][4];
    #pragma unroll
    for (int mt = 0; mt < 4; mt++)
        #pragma unroll
        for (int nt = 0; nt < 4; nt++)
            #pragma unroll
            for (int q = 0; q < 4; q++) acc[mt][nt][q] = 0.f;

    ldgA(0);
    stsA(0);
    cpB(0);
    ldgA(1);

    #pragma unroll 1
    for (int c = 0; c < NC; c++) {
        CP_WAIT0();
        __syncthreads();
        if (c + 1 < NC) { stsA(c + 1); cpB(c + 1); }
        if (c + 2 < NC) ldgA(c + 2);

        const uint32_t bA  = sb + (uint32_t)((c & 1) * STG);
        const uint32_t bBh = bA + PLANE_A;
        #pragma unroll
        for (int kt = 0; kt < 4; kt++) {
            uint32_t ah[4][4];
            #pragma unroll
            for (int mt = 0; mt < 4; mt++) {
                int r  = wm * 64 + mt * 16 + (lane & 15);
                int cb = kt * 32 + (lane >> 4) * 16;
                LDSM4(ah[mt], bA + (uint32_t)(r * PITCH + cb));
            }
            uint32_t bh[4][2];
            #pragma unroll
            for (int np = 0; np < 2; np++) {
                int r  = wn * 32 + np * 16 + (lane >> 4) * 8 + (lane & 7);
                int cb = kt * 32 + ((lane >> 3) & 1) * 16;
                uint32_t t[4];
                LDSM4(t, bBh + (uint32_t)(r * PITCH + cb));
                bh[2*np][0] = t[0]; bh[2*np][1] = t[1];
                bh[2*np+1][0] = t[2]; bh[2*np+1][1] = t[3];
            }
            #pragma unroll
            for (int mt = 0; mt < 4; mt++)
                #pragma unroll
                for (int nt = 0; nt < 4; nt++)
                    MMA_F16(acc[mt][nt], ah[mt], bh[nt]);
        }
    }
    __syncthreads();

    // ---- epilogue stage 1: fused a1/a2 (unchanged math) ----
    float* part = reinterpret_cast<float*>(smem);   // [8 wn][128][2]
    const int gh = cblk * 4 + (wn >> 1);
    float alv[4][2], arv[4][2];
    #pragma unroll
    for (int nt = 0; nt < 4; nt++) {
        int cih = (wn & 1) * 32 + nt * 8 + (lane & 3) * 2;
        alv[nt][0] = attn_l[gh * 64 + cih];
        alv[nt][1] = attn_l[gh * 64 + cih + 1];
        arv[nt][0] = attn_r[gh * 64 + cih];
        arv[nt][1] = attn_r[gh * 64 + cih + 1];
    }
    #pragma unroll
    for (int mt = 0; mt < 4; mt++) {
        int rloc = wm * 64 + mt * 16 + (lane >> 2);
        float s1a = 0.f, s2a = 0.f, s1b = 0.f, s2b = 0.f;
        #pragma unroll
        for (int nt = 0; nt < 4; nt++) {
            s1a += acc[mt][nt][0] * alv[nt][0] + acc[mt][nt][1] * alv[nt][1];
            s2a += acc[mt][nt][0] * arv[nt][0] + acc[mt][nt][1] * arv[nt][1];
            s1b += acc[mt][nt][2] * alv[nt][0] + acc[mt][nt][3] * alv[nt][1];
            s2b += acc[mt][nt][2] * arv[nt][0] + acc[mt][nt][3] * arv[nt][1];
        }
        #pragma unroll
        for (int off = 1; off <= 2; off <<= 1) {
            s1a += __shfl_xor_sync(0xffffffffu, s1a, off);
            s2a += __shfl_xor_sync(0xffffffffu, s2a, off);
            s1b += __shfl_xor_sync(0xffffffffu, s1b, off);
            s2b += __shfl_xor_sync(0xffffffffu, s2b, off);
        }
        if ((lane & 3) == 0) {
            part[(wn * 128 + rloc) * 2 + 0] = s1a;
            part[(wn * 128 + rloc) * 2 + 1] = s2a;
            part[(wn * 128 + rloc + 8) * 2 + 0] = s1b;
            part[(wn * 128 + rloc + 8) * 2 + 1] = s2b;
        }
    }
    __syncthreads();
    {
        int row = tid & 127;
        int h2  = tid >> 7;
        int n   = row0 + row;
        if (n < Nn) {
            float a1v = part[((2 * h2) * 128 + row) * 2 + 0] + part[((2 * h2 + 1) * 128 + row) * 2 + 0];
            float a2v = part[((2 * h2) * 128 + row) * 2 + 1] + part[((2 * h2 + 1) * 128 + row) * 2 + 1];
            g_a1[n * Hh + cblk * 4 + h2] = a1v;
            g_a2[n * Hh + cblk * 4 + h2] = a2v;
        }
    }
    __syncthreads();

    // ---- epilogue stage 2: ft stores, staged via smem for coalescing ----
    // tile: 32 rows x TPITCH(264) fp16; smem reused (a1/a2 done).
    {
        __half* tile = reinterpret_cast<__half*>(smem);
        const int lr = lane >> 2;       // 0..7
        const int l2 = lane & 3;        // 0..3
        #pragma unroll 1
        for (int mt = 0; mt < 4; mt++) {
            // STS: conflict-free (pitch 528B -> banks 4*lr + l2, all distinct)
            #pragma unroll
            for (int nt = 0; nt < 4; nt++) {
                int scol  = wn * 32 + nt * 8 + l2 * 2;
                int srow0 = wm * 16 + lr;
                *reinterpret_cast<uint32_t*>(&tile[srow0 * TPITCH + scol]) =
                    packf(acc[mt][nt][0], acc[mt][nt][1]);
                *reinterpret_cast<uint32_t*>(&tile[(srow0 + 8) * TPITCH + scol]) =
                    packf(acc[mt][nt][2], acc[mt][nt][3]);
            }
            __syncthreads();
            // readout: 32 rows x 512B fully-coalesced STG.128
            #pragma unroll
            for (int it = 0; it < 2; it++) {
                int idx = tid + it * 512;      // 0..1023
                int row = idx >> 5;            // 0..31 (srow)
                int ch  = idx & 31;            // 16B chunk within 512B row
                int grow = row0 + (row >> 4) * 64 + mt * 16 + (row & 15);
                if (grow < Nn) {
                    uint4 v = *reinterpret_cast<const uint4*>(
                        reinterpret_cast<const char*>(tile) + row * (TPITCH * 2) + ch * 16);
                    *reinterpret_cast<uint4*>(&g_ft[(size_t)grow * HD + col0 + ch * 8]) = v;
                }
            }
            __syncthreads();
        }
    }
}

// ---------------------------------------------------------------------------
// Kernel 2 (R13 exact): 2 warps per node, batch-2 loads, 5 CTAs/SM.
// dst = arange(E) % N.
// ---------------------------------------------------------------------------
__global__ __launch_bounds__(256, 5) void gat_agg7(
    const int* __restrict__ src,
    float* __restrict__ out)
{
    __shared__ float wsm[8][4][KEDGE];
    const int wrp  = threadIdx.x >> 5;
    const int lane = threadIdx.x & 31;
    const int d    = blockIdx.x * 4 + (wrp >> 1);
    const int wh   = wrp & 1;
    if (d >= Nn) return;

    float a2v[4];
    {
        float4 x = *reinterpret_cast<const float4*>(&g_a2[d * Hh + wh * 4]);
        a2v[0] = x.x; a2v[1] = x.y; a2v[2] = x.z; a2v[3] = x.w;
    }

    int s = 0;
    float e[4];
    if (lane < KEDGE) {
        s = src[d + lane * Nn];
        float4 x = *reinterpret_cast<const float4*>(&g_a1[s * Hh + wh * 4]);
        float t;
        t = x.x + a2v[0]; e[0] = t > 0.f ? t : LALPHA * t;
        t = x.y + a2v[1]; e[1] = t > 0.f ? t : LALPHA * t;
        t = x.z + a2v[2]; e[2] = t > 0.f ? t : LALPHA * t;
        t = x.w + a2v[3]; e[3] = t > 0.f ? t : LALPHA * t;
    } else {
        #pragma unroll
        for (int j = 0; j < 4; j++) e[j] = -CUDART_INF_F;
    }

    float m[4];
    #pragma unroll
    for (int j = 0; j < 4; j++) m[j] = e[j];
    #pragma unroll
    for (int off = 16; off > 0; off >>= 1)
        #pragma unroll
        for (int j = 0; j < 4; j++)
            m[j] = fmaxf(m[j], __shfl_xor_sync(0xffffffffu, m[j], off));

    float w[4], z[4];
    #pragma unroll
    for (int j = 0; j < 4; j++) { w[j] = __expf(e[j] - m[j]); z[j] = w[j]; }
    #pragma unroll
    for (int off = 16; off > 0; off >>= 1)
        #pragma unroll
        for (int j = 0; j < 4; j++)
            z[j] += __shfl_xor_sync(0xffffffffu, z[j], off);

    if (lane < KEDGE) {
        #pragma unroll
        for (int j = 0; j < 4; j++)
            wsm[wrp][j][lane] = w[j] / z[j];
    }
    __syncwarp();

    const int h = lane >> 3;
    float acc[8];
    #pragma unroll
    for (int q = 0; q < 8; q++) acc[q] = 0.f;

    const size_t cbase = (size_t)wh * 256 + lane * 8;
    #pragma unroll
    for (int kb = 0; kb < KEDGE / 2; kb++) {
        uint4 v[2];
        float wk[2];
        #pragma unroll
        for (int u = 0; u < 2; u++) {
            int k  = kb * 2 + u;
            int sk = __shfl_sync(0xffffffffu, s, k);
            v[u]  = *reinterpret_cast<const uint4*>(&g_ft[(size_t)sk * HD + cbase]);
            wk[u] = wsm[wrp][h][k];
        }
        #pragma unroll
        for (int u = 0; u < 2; u++) {
            const __half2* p = reinterpret_cast<const __half2*>(&v[u]);
            #pragma unroll
            for (int q = 0; q < 4; q++) {
                float2 f = __half22float2(p[q]);
                acc[2*q]   = fmaf(wk[u], f.x, acc[2*q]);
                acc[2*q+1] = fmaf(wk[u], f.y, acc[2*q+1]);
            }
        }
    }

    float* o = &out[(size_t)d * HD + cbase];
    *reinterpret_cast<float4*>(o)     = make_float4(acc[0], acc[1], acc[2], acc[3]);
    *reinterpret_cast<float4*>(o + 4) = make_float4(acc[4], acc[5], acc[6], acc[7]);
}

// ---------------------------------------------------------------------------
extern "C" void kernel_launch(void* const* d_in, const int* in_sizes, int n_in,
                              void* d_out, int out_size)
{
    const float* inputs = (const float*)d_in[0];
    const float* W      = (const float*)d_in[1];
    const float* attn_l = (const float*)d_in[2];
    const float* attn_r = (const float*)d_in[3];
    const int*   src    = (const int*)d_in[4];
    float* out = (float*)d_out;

    cudaFuncSetAttribute(gat_gemm10, cudaFuncAttributeMaxDynamicSharedMemorySize, SMEM_SZ);

    gat_splitW<<<(NW4 + 255) / 256, 256>>>(W);

    dim3 g1((Nn + MT - 1) / MT, 2);
    gat_gemm10<<<g1, 512, SMEM_SZ>>>(inputs, attn_l, attn_r);

    gat_agg7<<<(Nn + 3) / 4, 256>>>(src, out);
}

// round 16
// speedup vs baseline: 1.4467x; 1.4467x over previous
#include <cuda_runtime.h>
#include <cuda_fp16.h>
#include <math_constants.h>
#include <cstdint>

#define Nn 25000
#define IND 512
#define Hh 8
#define HD 512
#define KEDGE 16   // E/N inbound edges per node (dst = arange(E) % N)
#define LALPHA 0.2f

// ---- GEMM tiling ----
#define MT 128
#define NT 256
#define KC 64
#define NC (IND / KC)    // 8
#define PITCH 144        // 128B data + 16B pad (conflict-free ldmatrix)
#define PLANE_A (128 * PITCH)            // 18432 B
#define PLANE_B (256 * PITCH)            // 36864 B
#define STG (PLANE_A + PLANE_B)          // 55296 B
#define SMEM_SZ (2 * STG)                // 110592 B

// Scratch (allocation-free rule: __device__ globals)
__device__ __half g_ft[Nn * HD];       // projected features, fp16
__device__ __half g_Whi[IND * IND];    // fp16(W)
__device__ float  g_a1[Nn * Hh];
__device__ float  g_a2[Nn * Hh];

#define NW4 (IND * IND / 4)

__device__ __forceinline__ uint32_t smem_u32(const void* p) {
    uint32_t a;
    asm("{ .reg .u64 t; cvta.to.shared.u64 t, %1; cvt.u32.u64 %0, t; }" : "=r"(a) : "l"(p));
    return a;
}

#define LDSM4(r, addr) \
    asm volatile("ldmatrix.sync.aligned.m8n8.x4.shared.b16 {%0,%1,%2,%3}, [%4];" \
        : "=r"((r)[0]), "=r"((r)[1]), "=r"((r)[2]), "=r"((r)[3]) : "r"(addr))

#define MMA_F16(c, a, b) \
    asm volatile("mma.sync.aligned.m16n8k16.row.col.f32.f16.f16.f32 " \
        "{%0,%1,%2,%3}, {%4,%5,%6,%7}, {%8,%9}, {%0,%1,%2,%3};" \
        : "+f"((c)[0]), "+f"((c)[1]), "+f"((c)[2]), "+f"((c)[3]) \
        : "r"((a)[0]), "r"((a)[1]), "r"((a)[2]), "r"((a)[3]), "r"((b)[0]), "r"((b)[1]))

#define CP16(dst, src, p) \
    asm volatile("cp.async.cg.shared.global [%0], [%1], 16, %2;" \
        :: "r"(dst), "l"(src), "r"(p) : "memory")
#define CP_COMMIT() asm volatile("cp.async.commit_group;" ::: "memory")
#define CP_WAIT0()  asm volatile("cp.async.wait_group 0;" ::: "memory")

__device__ __forceinline__ uint32_t packf(float a, float b) {
    __half2 h = __floats2half2_rn(a, b);
    return *reinterpret_cast<uint32_t*>(&h);
}

// ---------------------------------------------------------------------------
// Kernel 0: W -> fp16 (tiny: 1.5 MB traffic)
// ---------------------------------------------------------------------------
__global__ __launch_bounds__(512) void gat_splitW(const float* __restrict__ W)
{
    int idx = blockIdx.x * 512 + threadIdx.x;
    if (idx < NW4) {
        float4 v = reinterpret_cast<const float4*>(W)[idx];
        uint2 hp = make_uint2(packf(v.x, v.y), packf(v.z, v.w));
        *reinterpret_cast<uint2*>(&g_Whi[(size_t)idx * 4]) = hp;
    }
}

// ---------------------------------------------------------------------------
// Kernel 1 (R13 structure — proven best): ft = fp16(A) @ Whi^T.
// A: fp32 LDG register-prefetch -> convert -> STS fp16. B: cp.async 2-stage.
// Sync: per-thread cp.async.wait THEN __syncthreads THEN read.
// Micro-tweak: ldgA(c+2) issues before cpB(c+1) (A loads start earlier).
// grid = (196, 2), 512 threads (16 warps: 2M x 8N). Fused a1/a2 epilogue.
// ---------------------------------------------------------------------------
__global__ __launch_bounds__(512, 1)
void gat_gemm6(const float* __restrict__ A,
               const float* __restrict__ attn_l,
               const float* __restrict__ attn_r)
{
    extern __shared__ char smem[];
    const uint32_t sb = smem_u32(smem);
    const int tid  = threadIdx.x;
    const int lane = tid & 31;
    const int wid  = tid >> 5;
    const int wm   = wid >> 3;      // 0..1
    const int wn   = wid & 7;       // 0..7
    const int row0 = blockIdx.x * MT;
    const int cblk = blockIdx.y;    // 0..1
    const int col0 = cblk * NT;

    const int r_a = tid >> 2;       // 0..127
    const int qa  = tid & 3;
    const int n_a = row0 + r_a;
    const bool a_ok = (n_a < Nn);
    const float* Abase = &A[(size_t)n_a * IND + qa * 16];

    const int r_ld = tid >> 3;      // 0..63
    const int q_ld = tid & 7;

    float4 ra[4];

    auto ldgA = [&](int c) {
        const int k0 = c * KC;
        if (a_ok) {
            #pragma unroll
            for (int j = 0; j < 4; j++)
                ra[j] = *reinterpret_cast<const float4*>(Abase + k0 + j * 4);
        } else {
            #pragma unroll
            for (int j = 0; j < 4; j++) ra[j] = make_float4(0.f, 0.f, 0.f, 0.f);
        }
    };
    auto stsA = [&](int c) {
        int off = (c & 1) * STG + r_a * PITCH + qa * 32;
        uint4 p0 = make_uint4(packf(ra[0].x, ra[0].y), packf(ra[0].z, ra[0].w),
                              packf(ra[1].x, ra[1].y), packf(ra[1].z, ra[1].w));
        uint4 p1 = make_uint4(packf(ra[2].x, ra[2].y), packf(ra[2].z, ra[2].w),
                              packf(ra[3].x, ra[3].y), packf(ra[3].z, ra[3].w));
        *reinterpret_cast<uint4*>(smem + off)      = p0;
        *reinterpret_cast<uint4*>(smem + off + 16) = p1;
    };
    auto cpB = [&](int c) {
        const int k0 = c * KC;
        const uint32_t base = sb + (uint32_t)((c & 1) * STG) + PLANE_A;
        #pragma unroll
        for (int it = 0; it < 4; it++) {
            int r = r_ld + it * 64;
            uint32_t dst = base + (uint32_t)(r * PITCH + q_ld * 16);
            const __half* sbh = &g_Whi[(size_t)(col0 + r) * IND + k0 + q_ld * 8];
            CP16(dst, sbh, 16);
        }
        CP_COMMIT();
    };

    float acc[4][4][4];
    #pragma unroll
    for (int mt = 0; mt < 4; mt++)
        #pragma unroll
        for (int nt = 0; nt < 4; nt++)
            #pragma unroll
            for (int q = 0; q < 4; q++) acc[mt][nt][q] = 0.f;

    ldgA(0);
    stsA(0);
    cpB(0);
    ldgA(1);

    #pragma unroll 1
    for (int c = 0; c < NC; c++) {
        CP_WAIT0();
        __syncthreads();
        if (c + 1 < NC) stsA(c + 1);
        if (c + 2 < NC) ldgA(c + 2);     // A LDGs issue before the cp.async burst
        if (c + 1 < NC) cpB(c + 1);

        const uint32_t bA  = sb + (uint32_t)((c & 1) * STG);
        const uint32_t bBh = bA + PLANE_A;
        #pragma unroll
        for (int kt = 0; kt < 4; kt++) {
            uint32_t ah[4][4];
            #pragma unroll
            for (int mt = 0; mt < 4; mt++) {
                int r  = wm * 64 + mt * 16 + (lane & 15);
                int cb = kt * 32 + (lane >> 4) * 16;
                LDSM4(ah[mt], bA + (uint32_t)(r * PITCH + cb));
            }
            uint32_t bh[4][2];
            #pragma unroll
            for (int np = 0; np < 2; np++) {
                int r  = wn * 32 + np * 16 + (lane >> 4) * 8 + (lane & 7);
                int cb = kt * 32 + ((lane >> 3) & 1) * 16;
                uint32_t t[4];
                LDSM4(t, bBh + (uint32_t)(r * PITCH + cb));
                bh[2*np][0] = t[0]; bh[2*np][1] = t[1];
                bh[2*np+1][0] = t[2]; bh[2*np+1][1] = t[3];
            }
            #pragma unroll
            for (int mt = 0; mt < 4; mt++)
                #pragma unroll
                for (int nt = 0; nt < 4; nt++)
                    MMA_F16(acc[mt][nt], ah[mt], bh[nt]);
        }
    }
    __syncthreads();

    // ---- epilogue (R13 exact): fp16 ft stores + fused a1/a2 ----
    float* part = reinterpret_cast<float*>(smem);   // [8 wn][128][2]
    const int gh = cblk * 4 + (wn >> 1);
    float alv[4][2], arv[4][2];
    #pragma unroll
    for (int nt = 0; nt < 4; nt++) {
        int cih = (wn & 1) * 32 + nt * 8 + (lane & 3) * 2;
        alv[nt][0] = attn_l[gh * 64 + cih];
        alv[nt][1] = attn_l[gh * 64 + cih + 1];
        arv[nt][0] = attn_r[gh * 64 + cih];
        arv[nt][1] = attn_r[gh * 64 + cih + 1];
    }
    #pragma unroll
    for (int mt = 0; mt < 4; mt++) {
        int rloc = wm * 64 + mt * 16 + (lane >> 2);
        int n0 = row0 + rloc;
        int n1 = n0 + 8;
        float s1a = 0.f, s2a = 0.f, s1b = 0.f, s2b = 0.f;
        #pragma unroll
        for (int nt = 0; nt < 4; nt++) {
            int gcol = col0 + wn * 32 + nt * 8 + (lane & 3) * 2;
            if (n0 < Nn)
                *reinterpret_cast<uint32_t*>(&g_ft[(size_t)n0 * HD + gcol]) =
                    packf(acc[mt][nt][0], acc[mt][nt][1]);
            if (n1 < Nn)
                *reinterpret_cast<uint32_t*>(&g_ft[(size_t)n1 * HD + gcol]) =
                    packf(acc[mt][nt][2], acc[mt][nt][3]);
            s1a += acc[mt][nt][0] * alv[nt][0] + acc[mt][nt][1] * alv[nt][1];
            s2a += acc[mt][nt][0] * arv[nt][0] + acc[mt][nt][1] * arv[nt][1];
            s1b += acc[mt][nt][2] * alv[nt][0] + acc[mt][nt][3] * alv[nt][1];
            s2b += acc[mt][nt][2] * arv[nt][0] + acc[mt][nt][3] * arv[nt][1];
        }
        #pragma unroll
        for (int off = 1; off <= 2; off <<= 1) {
            s1a += __shfl_xor_sync(0xffffffffu, s1a, off);
            s2a += __shfl_xor_sync(0xffffffffu, s2a, off);
            s1b += __shfl_xor_sync(0xffffffffu, s1b, off);
            s2b += __shfl_xor_sync(0xffffffffu, s2b, off);
        }
        if ((lane & 3) == 0) {
            part[(wn * 128 + rloc) * 2 + 0] = s1a;
            part[(wn * 128 + rloc) * 2 + 1] = s2a;
            part[(wn * 128 + rloc + 8) * 2 + 0] = s1b;
            part[(wn * 128 + rloc + 8) * 2 + 1] = s2b;
        }
    }
    __syncthreads();
    {
        int row = tid & 127;
        int h2  = tid >> 7;
        int n   = row0 + row;
        if (n < Nn) {
            float a1v = part[((2 * h2) * 128 + row) * 2 + 0] + part[((2 * h2 + 1) * 128 + row) * 2 + 0];
            float a2v = part[((2 * h2) * 128 + row) * 2 + 1] + part[((2 * h2 + 1) * 128 + row) * 2 + 1];
            g_a1[n * Hh + cblk * 4 + h2] = a1v;
            g_a2[n * Hh + cblk * 4 + h2] = a2v;
        }
    }
}

// ---------------------------------------------------------------------------
// Kernel 2 (R13 exact): 2 warps per node, batch-2 loads, 5 CTAs/SM.
// dst = arange(E) % N.
// ---------------------------------------------------------------------------
__global__ __launch_bounds__(256, 5) void gat_agg7(
    const int* __restrict__ src,
    float* __restrict__ out)
{
    __shared__ float wsm[8][4][KEDGE];
    const int wrp  = threadIdx.x >> 5;
    const int lane = threadIdx.x & 31;
    const int d    = blockIdx.x * 4 + (wrp >> 1);
    const int wh   = wrp & 1;
    if (d >= Nn) return;

    float a2v[4];
    {
        float4 x = *reinterpret_cast<const float4*>(&g_a2[d * Hh + wh * 4]);
        a2v[0] = x.x; a2v[1] = x.y; a2v[2] = x.z; a2v[3] = x.w;
    }

    int s = 0;
    float e[4];
    if (lane < KEDGE) {
        s = src[d + lane * Nn];
        float4 x = *reinterpret_cast<const float4*>(&g_a1[s * Hh + wh * 4]);
        float t;
        t = x.x + a2v[0]; e[0] = t > 0.f ? t : LALPHA * t;
        t = x.y + a2v[1]; e[1] = t > 0.f ? t : LALPHA * t;
        t = x.z + a2v[2]; e[2] = t > 0.f ? t : LALPHA * t;
        t = x.w + a2v[3]; e[3] = t > 0.f ? t : LALPHA * t;
    } else {
        #pragma unroll
        for (int j = 0; j < 4; j++) e[j] = -CUDART_INF_F;
    }

    float m[4];
    #pragma unroll
    for (int j = 0; j < 4; j++) m[j] = e[j];
    #pragma unroll
    for (int off = 16; off > 0; off >>= 1)
        #pragma unroll
        for (int j = 0; j < 4; j++)
            m[j] = fmaxf(m[j], __shfl_xor_sync(0xffffffffu, m[j], off));

    float w[4], z[4];
    #pragma unroll
    for (int j = 0; j < 4; j++) { w[j] = __expf(e[j] - m[j]); z[j] = w[j]; }
    #pragma unroll
    for (int off = 16; off > 0; off >>= 1)
        #pragma unroll
        for (int j = 0; j < 4; j++)
            z[j] += __shfl_xor_sync(0xffffffffu, z[j], off);

    if (lane < KEDGE) {
        #pragma unroll
        for (int j = 0; j < 4; j++)
            wsm[wrp][j][lane] = w[j] / z[j];
    }
    __syncwarp();

    const int h = lane >> 3;
    float acc[8];
    #pragma unroll
    for (int q = 0; q < 8; q++) acc[q] = 0.f;

    const size_t cbase = (size_t)wh * 256 + lane * 8;
    #pragma unroll
    for (int kb = 0; kb < KEDGE / 2; kb++) {
        uint4 v[2];
        float wk[2];
        #pragma unroll
        for (int u = 0; u < 2; u++) {
            int k  = kb * 2 + u;
            int sk = __shfl_sync(0xffffffffu, s, k);
            v[u]  = *reinterpret_cast<const uint4*>(&g_ft[(size_t)sk * HD + cbase]);
            wk[u] = wsm[wrp][h][k];
        }
        #pragma unroll
        for (int u = 0; u < 2; u++) {
            const __half2* p = reinterpret_cast<const __half2*>(&v[u]);
            #pragma unroll
            for (int q = 0; q < 4; q++) {
                float2 f = __half22float2(p[q]);
                acc[2*q]   = fmaf(wk[u], f.x, acc[2*q]);
                acc[2*q+1] = fmaf(wk[u], f.y, acc[2*q+1]);
            }
        }
    }

    float* o = &out[(size_t)d * HD + cbase];
    *reinterpret_cast<float4*>(o)     = make_float4(acc[0], acc[1], acc[2], acc[3]);
    *reinterpret_cast<float4*>(o + 4) = make_float4(acc[4], acc[5], acc[6], acc[7]);
}

// ---------------------------------------------------------------------------
extern "C" void kernel_launch(void* const* d_in, const int* in_sizes, int n_in,
                              void* d_out, int out_size)
{
    const float* inputs = (const float*)d_in[0];
    const float* W      = (const float*)d_in[1];
    const float* attn_l = (const float*)d_in[2];
    const float* attn_r = (const float*)d_in[3];
    const int*   src    = (const int*)d_in[4];
    float* out = (float*)d_out;

    cudaFuncSetAttribute(gat_gemm6, cudaFuncAttributeMaxDynamicSharedMemorySize, SMEM_SZ);

    gat_splitW<<<(NW4 + 511) / 512, 512>>>(W);

    dim3 g1((Nn + MT - 1) / MT, 2);
    gat_gemm6<<<g1, 512, SMEM_SZ>>>(inputs, attn_l, attn_r);

    gat_agg7<<<(Nn + 3) / 4, 256>>>(src, out);
}

// round 17
// speedup vs baseline: 1.5009x; 1.0375x over previous
#include <cuda_runtime.h>
#include <cuda_fp16.h>
#include <math_constants.h>
#include <cstdint>

#define Nn 25000
#define IND 512
#define Hh 8
#define HD 512
#define KEDGE 16   // E/N inbound edges per node (dst = arange(E) % N)
#define LALPHA 0.2f

// ---- GEMM tiling ----
#define MT 64
#define NT 256
#define KC 64
#define NC (IND / KC)    // 8
#define PITCH 144        // 128B data + 16B pad (conflict-free ldmatrix)
#define PLANE_A (64 * PITCH)             // 9216 B
#define PLANE_B (256 * PITCH)            // 36864 B
#define STG (PLANE_A + PLANE_B)          // 46080 B
#define SMEM_SZ (2 * STG)                // 92160 B (2 CTAs/SM -> 180 KB)

// Scratch (allocation-free rule: __device__ globals)
__device__ __half g_ft[Nn * HD];       // projected features, fp16
__device__ __half g_Whi[IND * IND];    // fp16(W)
__device__ float  g_a1[Nn * Hh];
__device__ float  g_a2[Nn * Hh];

#define NW4 (IND * IND / 4)

__device__ __forceinline__ uint32_t smem_u32(const void* p) {
    uint32_t a;
    asm("{ .reg .u64 t; cvta.to.shared.u64 t, %1; cvt.u32.u64 %0, t; }" : "=r"(a) : "l"(p));
    return a;
}

#define LDSM4(r, addr) \
    asm volatile("ldmatrix.sync.aligned.m8n8.x4.shared.b16 {%0,%1,%2,%3}, [%4];" \
        : "=r"((r)[0]), "=r"((r)[1]), "=r"((r)[2]), "=r"((r)[3]) : "r"(addr))

#define MMA_F16(c, a, b) \
    asm volatile("mma.sync.aligned.m16n8k16.row.col.f32.f16.f16.f32 " \
        "{%0,%1,%2,%3}, {%4,%5,%6,%7}, {%8,%9}, {%0,%1,%2,%3};" \
        : "+f"((c)[0]), "+f"((c)[1]), "+f"((c)[2]), "+f"((c)[3]) \
        : "r"((a)[0]), "r"((a)[1]), "r"((a)[2]), "r"((a)[3]), "r"((b)[0]), "r"((b)[1]))

#define CP16(dst, src, p) \
    asm volatile("cp.async.cg.shared.global [%0], [%1], 16, %2;" \
        :: "r"(dst), "l"(src), "r"(p) : "memory")
#define CP_COMMIT() asm volatile("cp.async.commit_group;" ::: "memory")
#define CP_WAIT0()  asm volatile("cp.async.wait_group 0;" ::: "memory")

__device__ __forceinline__ uint32_t packf(float a, float b) {
    __half2 h = __floats2half2_rn(a, b);
    return *reinterpret_cast<uint32_t*>(&h);
}

// ---------------------------------------------------------------------------
// Kernel 0: W -> fp16 (R13 form: 256 threads — fastest measured)
// ---------------------------------------------------------------------------
__global__ __launch_bounds__(256) void gat_splitW(const float* __restrict__ W)
{
    int idx = blockIdx.x * 256 + threadIdx.x;
    if (idx < NW4) {
        float4 v = reinterpret_cast<const float4*>(W)[idx];
        uint2 hp = make_uint2(packf(v.x, v.y), packf(v.z, v.w));
        *reinterpret_cast<uint2*>(&g_Whi[(size_t)idx * 4]) = hp;
    }
}

// ---------------------------------------------------------------------------
// Kernel 1: ft = fp16(A) @ Whi^T. R13 pipeline, CTA tile 64M x 256N,
// 256 threads (8 warps: 1M x 8N), 2 CTAs/SM (wave-quantization fix).
// A: fp32 LDG prefetch -> cvt -> STS. B: cp.async 2-stage.
// Sync: per-thread cp.async.wait THEN __syncthreads THEN read.
// grid = (391, 2). Fused a1/a2 epilogue.
// ---------------------------------------------------------------------------
__global__ __launch_bounds__(256, 2)
void gat_gemm11(const float* __restrict__ A,
                const float* __restrict__ attn_l,
                const float* __restrict__ attn_r)
{
    extern __shared__ char smem[];
    const uint32_t sb = smem_u32(smem);
    const int tid  = threadIdx.x;
    const int lane = tid & 31;
    const int wn   = tid >> 5;      // warp 0..7 -> N slice
    const int row0 = blockIdx.x * MT;
    const int cblk = blockIdx.y;    // 0..1
    const int col0 = cblk * NT;

    // A loader: 64 rows x 16 float4/row = 1024 float4 / 256 thr = 4 each
    const int r_a = tid >> 2;       // 0..63
    const int qa  = tid & 3;
    const int n_a = row0 + r_a;
    const bool a_ok = (n_a < Nn);
    const float* Abase = &A[(size_t)n_a * IND + qa * 16];

    // B loader: 256 rows x 8 chunks = 2048 / 256 thr = 8 each
    const int r_ld = tid >> 3;      // 0..31
    const int q_ld = tid & 7;

    float4 ra[4];

    auto ldgA = [&](int c) {
        const int k0 = c * KC;
        if (a_ok) {
            #pragma unroll
            for (int j = 0; j < 4; j++)
                ra[j] = *reinterpret_cast<const float4*>(Abase + k0 + j * 4);
        } else {
            #pragma unroll
            for (int j = 0; j < 4; j++) ra[j] = make_float4(0.f, 0.f, 0.f, 0.f);
        }
    };
    auto stsA = [&](int c) {
        int off = (c & 1) * STG + r_a * PITCH + qa * 32;
        uint4 p0 = make_uint4(packf(ra[0].x, ra[0].y), packf(ra[0].z, ra[0].w),
                              packf(ra[1].x, ra[1].y), packf(ra[1].z, ra[1].w));
        uint4 p1 = make_uint4(packf(ra[2].x, ra[2].y), packf(ra[2].z, ra[2].w),
                              packf(ra[3].x, ra[3].y), packf(ra[3].z, ra[3].w));
        *reinterpret_cast<uint4*>(smem + off)      = p0;
        *reinterpret_cast<uint4*>(smem + off + 16) = p1;
    };
    auto cpB = [&](int c) {
        const int k0 = c * KC;
        const uint32_t base = sb + (uint32_t)((c & 1) * STG) + PLANE_A;
        #pragma unroll
        for (int it = 0; it < 8; it++) {
            int r = r_ld + it * 32;
            uint32_t dst = base + (uint32_t)(r * PITCH + q_ld * 16);
            const __half* sbh = &g_Whi[(size_t)(col0 + r) * IND + k0 + q_ld * 8];
            CP16(dst, sbh, 16);
        }
        CP_COMMIT();
    };

    float acc[4][4][4];
    #pragma unroll
    for (int mt = 0; mt < 4; mt++)
        #pragma unroll
        for (int nt = 0; nt < 4; nt++)
            #pragma unroll
            for (int q = 0; q < 4; q++) acc[mt][nt][q] = 0.f;

    ldgA(0);
    stsA(0);
    cpB(0);
    ldgA(1);

    #pragma unroll 1
    for (int c = 0; c < NC; c++) {
        CP_WAIT0();
        __syncthreads();
        if (c + 1 < NC) { stsA(c + 1); cpB(c + 1); }
        if (c + 2 < NC) ldgA(c + 2);

        const uint32_t bA  = sb + (uint32_t)((c & 1) * STG);
        const uint32_t bBh = bA + PLANE_A;
        #pragma unroll
        for (int kt = 0; kt < 4; kt++) {
            uint32_t ah[4][4];
            #pragma unroll
            for (int mt = 0; mt < 4; mt++) {
                int r  = mt * 16 + (lane & 15);
                int cb = kt * 32 + (lane >> 4) * 16;
                LDSM4(ah[mt], bA + (uint32_t)(r * PITCH + cb));
            }
            uint32_t bh[4][2];
            #pragma unroll
            for (int np = 0; np < 2; np++) {
                int r  = wn * 32 + np * 16 + (lane >> 4) * 8 + (lane & 7);
                int cb = kt * 32 + ((lane >> 3) & 1) * 16;
                uint32_t t[4];
                LDSM4(t, bBh + (uint32_t)(r * PITCH + cb));
                bh[2*np][0] = t[0]; bh[2*np][1] = t[1];
                bh[2*np+1][0] = t[2]; bh[2*np+1][1] = t[3];
            }
            #pragma unroll
            for (int mt = 0; mt < 4; mt++)
                #pragma unroll
                for (int nt = 0; nt < 4; nt++)
                    MMA_F16(acc[mt][nt], ah[mt], bh[nt]);
        }
    }
    __syncthreads();

    // ---- epilogue: fp16 ft stores + fused a1/a2 ----
    float* part = reinterpret_cast<float*>(smem);   // [8 wn][64][2]
    const int gh = cblk * 4 + (wn >> 1);            // global head
    float alv[4][2], arv[4][2];
    #pragma unroll
    for (int nt = 0; nt < 4; nt++) {
        int cih = (wn & 1) * 32 + nt * 8 + (lane & 3) * 2;
        alv[nt][0] = attn_l[gh * 64 + cih];
        alv[nt][1] = attn_l[gh * 64 + cih + 1];
        arv[nt][0] = attn_r[gh * 64 + cih];
        arv[nt][1] = attn_r[gh * 64 + cih + 1];
    }
    #pragma unroll
    for (int mt = 0; mt < 4; mt++) {
        int rloc = mt * 16 + (lane >> 2);           // 0..63
        int n0 = row0 + rloc;
        int n1 = n0 + 8;
        float s1a = 0.f, s2a = 0.f, s1b = 0.f, s2b = 0.f;
        #pragma unroll
        for (int nt = 0; nt < 4; nt++) {
            int gcol = col0 + wn * 32 + nt * 8 + (lane & 3) * 2;
            if (n0 < Nn)
                *reinterpret_cast<uint32_t*>(&g_ft[(size_t)n0 * HD + gcol]) =
                    packf(acc[mt][nt][0], acc[mt][nt][1]);
            if (n1 < Nn)
                *reinterpret_cast<uint32_t*>(&g_ft[(size_t)n1 * HD + gcol]) =
                    packf(acc[mt][nt][2], acc[mt][nt][3]);
            s1a += acc[mt][nt][0] * alv[nt][0] + acc[mt][nt][1] * alv[nt][1];
            s2a += acc[mt][nt][0] * arv[nt][0] + acc[mt][nt][1] * arv[nt][1];
            s1b += acc[mt][nt][2] * alv[nt][0] + acc[mt][nt][3] * alv[nt][1];
            s2b += acc[mt][nt][2] * arv[nt][0] + acc[mt][nt][3] * arv[nt][1];
        }
        #pragma unroll
        for (int off = 1; off <= 2; off <<= 1) {
            s1a += __shfl_xor_sync(0xffffffffu, s1a, off);
            s2a += __shfl_xor_sync(0xffffffffu, s2a, off);
            s1b += __shfl_xor_sync(0xffffffffu, s1b, off);
            s2b += __shfl_xor_sync(0xffffffffu, s2b, off);
        }
        if ((lane & 3) == 0) {
            part[(wn * 64 + rloc) * 2 + 0] = s1a;
            part[(wn * 64 + rloc) * 2 + 1] = s2a;
            part[(wn * 64 + rloc + 8) * 2 + 0] = s1b;
            part[(wn * 64 + rloc + 8) * 2 + 1] = s2b;
        }
    }
    __syncthreads();
    {
        int row = tid & 63;              // 0..63
        int h2  = tid >> 6;              // 0..3: head within CTA
        int n   = row0 + row;
        if (n < Nn) {
            float a1v = part[((2 * h2) * 64 + row) * 2 + 0] + part[((2 * h2 + 1) * 64 + row) * 2 + 0];
            float a2v = part[((2 * h2) * 64 + row) * 2 + 1] + part[((2 * h2 + 1) * 64 + row) * 2 + 1];
            g_a1[n * Hh + cblk * 4 + h2] = a1v;
            g_a2[n * Hh + cblk * 4 + h2] = a2v;
        }
    }
}

// ---------------------------------------------------------------------------
// Kernel 2 (R13 exact): 2 warps per node, batch-2 loads, 5 CTAs/SM.
// dst = arange(E) % N.
// ---------------------------------------------------------------------------
__global__ __launch_bounds__(256, 5) void gat_agg7(
    const int* __restrict__ src,
    float* __restrict__ out)
{
    __shared__ float wsm[8][4][KEDGE];
    const int wrp  = threadIdx.x >> 5;
    const int lane = threadIdx.x & 31;
    const int d    = blockIdx.x * 4 + (wrp >> 1);
    const int wh   = wrp & 1;
    if (d >= Nn) return;

    float a2v[4];
    {
        float4 x = *reinterpret_cast<const float4*>(&g_a2[d * Hh + wh * 4]);
        a2v[0] = x.x; a2v[1] = x.y; a2v[2] = x.z; a2v[3] = x.w;
    }

    int s = 0;
    float e[4];
    if (lane < KEDGE) {
        s = src[d + lane * Nn];
        float4 x = *reinterpret_cast<const float4*>(&g_a1[s * Hh + wh * 4]);
        float t;
        t = x.x + a2v[0]; e[0] = t > 0.f ? t : LALPHA * t;
        t = x.y + a2v[1]; e[1] = t > 0.f ? t : LALPHA * t;
        t = x.z + a2v[2]; e[2] = t > 0.f ? t : LALPHA * t;
        t = x.w + a2v[3]; e[3] = t > 0.f ? t : LALPHA * t;
    } else {
        #pragma unroll
        for (int j = 0; j < 4; j++) e[j] = -CUDART_INF_F;
    }

    float m[4];
    #pragma unroll
    for (int j = 0; j < 4; j++) m[j] = e[j];
    #pragma unroll
    for (int off = 16; off > 0; off >>= 1)
        #pragma unroll
        for (int j = 0; j < 4; j++)
            m[j] = fmaxf(m[j], __shfl_xor_sync(0xffffffffu, m[j], off));

    float w[4], z[4];
    #pragma unroll
    for (int j = 0; j < 4; j++) { w[j] = __expf(e[j] - m[j]); z[j] = w[j]; }
    #pragma unroll
    for (int off = 16; off > 0; off >>= 1)
        #pragma unroll
        for (int j = 0; j < 4; j++)
            z[j] += __shfl_xor_sync(0xffffffffu, z[j], off);

    if (lane < KEDGE) {
        #pragma unroll
        for (int j = 0; j < 4; j++)
            wsm[wrp][j][lane] = w[j] / z[j];
    }
    __syncwarp();

    const int h = lane >> 3;
    float acc[8];
    #pragma unroll
    for (int q = 0; q < 8; q++) acc[q] = 0.f;

    const size_t cbase = (size_t)wh * 256 + lane * 8;
    #pragma unroll
    for (int kb = 0; kb < KEDGE / 2; kb++) {
        uint4 v[2];
        float wk[2];
        #pragma unroll
        for (int u = 0; u < 2; u++) {
            int k  = kb * 2 + u;
            int sk = __shfl_sync(0xffffffffu, s, k);
            v[u]  = *reinterpret_cast<const uint4*>(&g_ft[(size_t)sk * HD + cbase]);
            wk[u] = wsm[wrp][h][k];
        }
        #pragma unroll
        for (int u = 0; u < 2; u++) {
            const __half2* p = reinterpret_cast<const __half2*>(&v[u]);
            #pragma unroll
            for (int q = 0; q < 4; q++) {
                float2 f = __half22float2(p[q]);
                acc[2*q]   = fmaf(wk[u], f.x, acc[2*q]);
                acc[2*q+1] = fmaf(wk[u], f.y, acc[2*q+1]);
            }
        }
    }

    float* o = &out[(size_t)d * HD + cbase];
    *reinterpret_cast<float4*>(o)     = make_float4(acc[0], acc[1], acc[2], acc[3]);
    *reinterpret_cast<float4*>(o + 4) = make_float4(acc[4], acc[5], acc[6], acc[7]);
}

// ---------------------------------------------------------------------------
extern "C" void kernel_launch(void* const* d_in, const int* in_sizes, int n_in,
                              void* d_out, int out_size)
{
    const float* inputs = (const float*)d_in[0];
    const float* W      = (const float*)d_in[1];
    const float* attn_l = (const float*)d_in[2];
    const float* attn_r = (const float*)d_in[3];
    const int*   src    = (const int*)d_in[4];
    float* out = (float*)d_out;

    cudaFuncSetAttribute(gat_gemm11, cudaFuncAttributeMaxDynamicSharedMemorySize, SMEM_SZ);

    gat_splitW<<<(NW4 + 255) / 256, 256>>>(W);

    dim3 g1((Nn + MT - 1) / MT, 2);
    gat_gemm11<<<g1, 256, SMEM_SZ>>>(inputs, attn_l, attn_r);

    gat_agg7<<<(Nn + 3) / 4, 256>>>(src, out);
}